// round 1
// baseline (speedup 1.0000x reference)
#include <cuda_runtime.h>
#include <cooperative_groups.h>
#include <cstdint>

namespace cg = cooperative_groups;

#define Bn   8
#define Nn   32768
#define FDn  32
#define NGn  1024
#define GSn  32
#define FPS_C 8       // CTAs per cluster (one cluster per batch)
#define FPS_T 1024    // threads per FPS CTA
#define FPS_P 4       // points per thread: 8*1024*4 = 32768
#define CHUNK 2048    // kNN smem tile (points)

// Scratch (no allocations allowed): packed coords + FPS-selected indices
__device__ float4 g_packed[Bn * Nn];     // 4 MB
__device__ int    g_sidx[Bn * NGn];      // global point index of each sample

// Exact (non-FMA, left-to-right) squared distance, matching XLA's
// sum((a-b)**2) elementwise f32 semantics.
__device__ __forceinline__ float d2f(float ax, float ay, float az,
                                     float bx, float by, float bz) {
    float dx = ax - bx, dy = ay - by, dz = az - bz;
    return __fadd_rn(__fadd_rn(__fmul_rn(dx, dx), __fmul_rn(dy, dy)),
                     __fmul_rn(dz, dz));
}

// argmax semantics: larger d wins; tie -> smaller index (jnp.argmax = first max)
__device__ __forceinline__ bool maxbetter(float d1, int i1, float d2_, int i2) {
    return (d1 > d2_) || (d1 == d2_ && i1 < i2);
}

// ---------------------------------------------------------------------------
// Kernel 1: pack coords [N,3] AoS -> float4 SoA-ish padded array
// ---------------------------------------------------------------------------
__global__ void pack_kernel(const float* __restrict__ coord) {
    int i = blockIdx.x * blockDim.x + threadIdx.x;
    if (i < Bn * Nn) {
        g_packed[i] = make_float4(coord[3 * i], coord[3 * i + 1],
                                  coord[3 * i + 2], 0.f);
    }
}

// ---------------------------------------------------------------------------
// Kernel 2: FPS. One 8-CTA cluster per batch. Each thread owns 4 points
// (coords + running min-dist live in registers). Per iteration:
//   warp shfl-reduce -> CTA smem reduce -> DSMEM all-to-all candidate
//   exchange (double-buffered) -> cluster.sync -> winner known everywhere.
// Candidate coords are carried through the reduction so the update never
// touches global memory on the critical path.
// ---------------------------------------------------------------------------
__global__ void __cluster_dims__(FPS_C, 1, 1) __launch_bounds__(FPS_T, 1)
fps_kernel() {
    __shared__ float s_d[32], s_x[32], s_y[32], s_z[32];
    __shared__ int   s_i[32];
    __shared__ float c_d[2][FPS_C], c_x[2][FPS_C], c_y[2][FPS_C], c_z[2][FPS_C];
    __shared__ int   c_i[2][FPS_C];

    cg::cluster_group cluster = cg::this_cluster();
    unsigned rank = cluster.block_rank();
    int tid = threadIdx.x, lane = tid & 31, wid = tid >> 5;
    int b = blockIdx.x / FPS_C;
    int base = b * Nn + (int)rank * (Nn / FPS_C) + tid * FPS_P;

    float px[FPS_P], py[FPS_P], pz[FPS_P], dist[FPS_P];
#pragma unroll
    for (int j = 0; j < FPS_P; j++) {
        float4 q = g_packed[base + j];
        px[j] = q.x; py[j] = q.y; pz[j] = q.z;
    }

    // init: distance to point 0 of this batch (== state after selecting s0=0)
    float4 p0 = g_packed[b * Nn];
    float bd = -1.f; int bi = 0x7fffffff;
    float bx = 0.f, by = 0.f, bz = 0.f;
#pragma unroll
    for (int j = 0; j < FPS_P; j++) {
        float d = d2f(px[j], py[j], pz[j], p0.x, p0.y, p0.z);
        dist[j] = d;
        if (maxbetter(d, base + j, bd, bi)) {
            bd = d; bi = base + j; bx = px[j]; by = py[j]; bz = pz[j];
        }
    }
    if (rank == 0 && tid == 0) g_sidx[b * NGn + 0] = b * Nn;  // s_idx[0] = 0

    for (int k = 1; k < NGn; k++) {
        int kb = k & 1;
        // warp xor-reduce carrying (d, idx, x, y, z)
#pragma unroll
        for (int o = 16; o; o >>= 1) {
            float od = __shfl_xor_sync(~0u, bd, o);
            int   oi = __shfl_xor_sync(~0u, bi, o);
            float ox = __shfl_xor_sync(~0u, bx, o);
            float oy = __shfl_xor_sync(~0u, by, o);
            float oz = __shfl_xor_sync(~0u, bz, o);
            if (maxbetter(od, oi, bd, bi)) { bd = od; bi = oi; bx = ox; by = oy; bz = oz; }
        }
        if (lane == 0) { s_d[wid] = bd; s_i[wid] = bi; s_x[wid] = bx; s_y[wid] = by; s_z[wid] = bz; }
        __syncthreads();
        if (wid == 0) {
            float rd = s_d[lane]; int ri = s_i[lane];
            float rx = s_x[lane], ry = s_y[lane], rz = s_z[lane];
#pragma unroll
            for (int o = 16; o; o >>= 1) {
                float od = __shfl_xor_sync(~0u, rd, o);
                int   oi = __shfl_xor_sync(~0u, ri, o);
                float ox = __shfl_xor_sync(~0u, rx, o);
                float oy = __shfl_xor_sync(~0u, ry, o);
                float oz = __shfl_xor_sync(~0u, rz, o);
                if (maxbetter(od, oi, rd, ri)) { rd = od; ri = oi; rx = ox; ry = oy; rz = oz; }
            }
            // lanes 0..7 broadcast this CTA's candidate into every CTA's slot [rank]
            if (lane < FPS_C) {
                *cluster.map_shared_rank(&c_d[kb][rank], lane) = rd;
                *cluster.map_shared_rank(&c_i[kb][rank], lane) = ri;
                *cluster.map_shared_rank(&c_x[kb][rank], lane) = rx;
                *cluster.map_shared_rank(&c_y[kb][rank], lane) = ry;
                *cluster.map_shared_rank(&c_z[kb][rank], lane) = rz;
            }
        }
        cluster.sync();
        // every thread picks the global winner from the 8 candidates
        float wd = c_d[kb][0]; int wi = c_i[kb][0];
        float wx = c_x[kb][0], wy = c_y[kb][0], wz = c_z[kb][0];
#pragma unroll
        for (int r = 1; r < FPS_C; r++) {
            float rd = c_d[kb][r]; int ri = c_i[kb][r];
            if (maxbetter(rd, ri, wd, wi)) {
                wd = rd; wi = ri; wx = c_x[kb][r]; wy = c_y[kb][r]; wz = c_z[kb][r];
            }
        }
        if (rank == 0 && tid == 0) g_sidx[b * NGn + k] = wi;
        // update dists with the winner; fuse next iteration's local best
        bd = -1.f; bi = 0x7fffffff;
#pragma unroll
        for (int j = 0; j < FPS_P; j++) {
            float nd = d2f(px[j], py[j], pz[j], wx, wy, wz);
            float mn = fminf(dist[j], nd);
            dist[j] = mn;
            if (maxbetter(mn, base + j, bd, bi)) {
                bd = mn; bi = base + j; bx = px[j]; by = py[j]; bz = pz[j];
            }
        }
    }
}

// ---------------------------------------------------------------------------
// Kernel 3: kNN (top-32 by (d2, idx) lex order) + angle/curvature + outputs.
// One warp per sample (32 warps/CTA share a smem coord tile). Each lane holds
// one kept candidate; threshold = warp lex-max of kept set; ballot-filtered
// serial insertion keeps the hot loop tiny.
// ---------------------------------------------------------------------------
__global__ void __launch_bounds__(1024, 1)
knn_kernel(const float* __restrict__ coord, const float* __restrict__ feat,
           const int* __restrict__ labels, float* __restrict__ out) {
    __shared__ float4 sc[CHUNK];
    const unsigned FULL = 0xffffffffu;
    int tid = threadIdx.x, lane = tid & 31, wid = tid >> 5;
    int s = blockIdx.x * 32 + wid;   // sample id [0, 8192)
    int b = s >> 10;                 // batch (1024 samples/batch)
    int si = g_sidx[s];              // global point idx of this sample
    float4 sp = g_packed[si];

    float kd = 3.4028235e38f; int ki = 0x7fffffff;          // kept (per lane)
    float tmd = 3.4028235e38f; int tmi = 0x7fffffff; int tml = 0;  // lex-max of kept

    for (int c = 0; c < Nn / CHUNK; c++) {
        int cb = c * CHUNK;
        __syncthreads();
#pragma unroll
        for (int e = tid; e < CHUNK; e += 1024)
            sc[e] = g_packed[b * Nn + cb + e];
        __syncthreads();
        for (int j = 0; j < CHUNK / 32; j++) {
            float4 q = sc[j * 32 + lane];
            int gi = b * Nn + cb + j * 32 + lane;
            float d2 = d2f(sp.x, sp.y, sp.z, q.x, q.y, q.z);
            unsigned m = __ballot_sync(FULL, (d2 < tmd) || (d2 == tmd && gi < tmi));
            while (m) {
                int src = __ffs(m) - 1; m &= m - 1;
                float cd = __shfl_sync(FULL, d2, src);
                int   ci = __shfl_sync(FULL, gi, src);
                if ((cd < tmd) || (cd == tmd && ci < tmi)) {   // uniform branch
                    if (lane == tml) { kd = cd; ki = ci; }
                    float md = kd; int mi = ki; int ml = lane;
#pragma unroll
                    for (int o = 16; o; o >>= 1) {
                        float od = __shfl_xor_sync(FULL, md, o);
                        int   oi = __shfl_xor_sync(FULL, mi, o);
                        int   ol = __shfl_xor_sync(FULL, ml, o);
                        if (od > md || (od == md && (oi < mi || (oi == mi && ol < ml)))) {
                            md = od; mi = oi; ml = ol;
                        }
                    }
                    tmd = md; tmi = mi; tml = ml;
                }
            }
        }
    }

    // ---- angles: angle = 2*atan2(sqrt(t - a.b), sqrt(t + a.b)), t=|a||b| ----
    float a_own = feat[si * FDn + lane];
    float dot = 0.f, an2 = 0.f, bn2 = 0.f;
    const float4* frow = (const float4*)(feat + (size_t)ki * FDn);
#pragma unroll
    for (int g = 0; g < FDn / 4; g++) {
        float4 bv = frow[g];
        float a0 = __shfl_sync(FULL, a_own, g * 4 + 0);
        float a1 = __shfl_sync(FULL, a_own, g * 4 + 1);
        float a2 = __shfl_sync(FULL, a_own, g * 4 + 2);
        float a3 = __shfl_sync(FULL, a_own, g * 4 + 3);
        dot = fmaf(a0, bv.x, dot); an2 = fmaf(a0, a0, an2); bn2 = fmaf(bv.x, bv.x, bn2);
        dot = fmaf(a1, bv.y, dot); an2 = fmaf(a1, a1, an2); bn2 = fmaf(bv.y, bv.y, bn2);
        dot = fmaf(a2, bv.z, dot); an2 = fmaf(a2, a2, an2); bn2 = fmaf(bv.z, bv.z, bn2);
        dot = fmaf(a3, bv.w, dot); an2 = fmaf(a3, a3, an2); bn2 = fmaf(bv.w, bv.w, bn2);
    }
    float t = sqrtf(an2) * sqrtf(bn2);
    float ang = 2.f * atan2f(sqrtf(fmaxf(t - dot, 0.f)), sqrtf(fmaxf(t + dot, 0.f)));
    if (ki == si) ang = 0.f;   // exclude self (the sorted-nearest neighbor)
    float ssum = ang;
#pragma unroll
    for (int o = 16; o; o >>= 1) ssum += __shfl_xor_sync(FULL, ssum, o);
    float pc = ssum / 31.f;

    // ---- outputs (tuple flattened+concatenated as float32) ----
    const int OFF_FEAT = Bn * NGn * 3;
    const int OFF_SW   = OFF_FEAT + Bn * NGn * (FDn + 1);
    const int OFF_LAB  = OFF_SW + Bn * NGn;
    const int OFF_SIDX = OFF_LAB + Bn * NGn;
    if (lane < 3) out[s * 3 + lane] = coord[si * 3 + lane];
    out[OFF_FEAT + s * 33 + lane] = a_own;
    if (lane == 0) {
        out[OFF_FEAT + s * 33 + 32] = pc;
        out[OFF_SW + s]   = pc > 0.087266f ? 1.f : 0.f;
        out[OFF_LAB + s]  = (float)labels[si];
        out[OFF_SIDX + s] = (float)si;
    }
}

// ---------------------------------------------------------------------------
extern "C" void kernel_launch(void* const* d_in, const int* in_sizes, int n_in,
                              void* d_out, int out_size) {
    const float* coord  = (const float*)d_in[0];
    const float* feat   = (const float*)d_in[1];
    const int*   labels = (const int*)d_in[2];
    float* out = (float*)d_out;

    pack_kernel<<<(Bn * Nn + 255) / 256, 256>>>(coord);
    fps_kernel<<<Bn * FPS_C, FPS_T>>>();
    knn_kernel<<<(Bn * NGn) / 32, 1024>>>(coord, feat, labels, out);
}

// round 2
// speedup vs baseline: 1.3406x; 1.3406x over previous
#include <cuda_runtime.h>
#include <cstdint>

#define Bn   8
#define Nn   32768
#define FDn  32
#define NGn  1024
#define CHUNK 2048    // kNN smem tile (points)

// Scratch (no allocations allowed): packed coords + FPS-selected indices
__device__ float4 g_packed[Bn * Nn];     // 4 MB
__device__ int    g_sidx[Bn * NGn];      // global point index of each sample

// Exact (non-FMA, left-to-right) squared distance, matching XLA's
// sum((a-b)**2) elementwise f32 semantics.
__device__ __forceinline__ float d2f(float ax, float ay, float az,
                                     float bx, float by, float bz) {
    float dx = ax - bx, dy = ay - by, dz = az - bz;
    return __fadd_rn(__fadd_rn(__fmul_rn(dx, dx), __fmul_rn(dy, dy)),
                     __fmul_rn(dz, dz));
}

// ---------------------------------------------------------------------------
// small PTX helpers
// ---------------------------------------------------------------------------
__device__ __forceinline__ uint32_t s2u(const void* p) {
    return (uint32_t)__cvta_generic_to_shared(p);
}
__device__ __forceinline__ uint32_t ctarank() {
    uint32_t r; asm("mov.u32 %0, %%cluster_ctarank;" : "=r"(r)); return r;
}
__device__ __forceinline__ uint32_t mapa_u32(uint32_t addr, uint32_t rank) {
    uint32_t r;
    asm("mapa.shared::cluster.u32 %0, %1, %2;" : "=r"(r) : "r"(addr), "r"(rank));
    return r;
}
__device__ __forceinline__ void st_async_u64(uint32_t raddr, unsigned long long v,
                                             uint32_t rmbar) {
    asm volatile("st.async.shared::cluster.mbarrier::complete_tx::bytes.u64 [%0], %1, [%2];"
                 :: "r"(raddr), "l"(v), "r"(rmbar) : "memory");
}
__device__ __forceinline__ void st_async_u32(uint32_t raddr, uint32_t v,
                                             uint32_t rmbar) {
    asm volatile("st.async.shared::cluster.mbarrier::complete_tx::bytes.u32 [%0], %1, [%2];"
                 :: "r"(raddr), "r"(v), "r"(rmbar) : "memory");
}
__device__ __forceinline__ void mbar_init(uint32_t addr, uint32_t cnt) {
    asm volatile("mbarrier.init.shared.b64 [%0], %1;" :: "r"(addr), "r"(cnt) : "memory");
}
__device__ __forceinline__ void mbar_expect_tx(uint32_t addr, uint32_t bytes) {
    asm volatile("mbarrier.arrive.expect_tx.shared.b64 _, [%0], %1;"
                 :: "r"(addr), "r"(bytes) : "memory");
}
__device__ __forceinline__ void mbar_wait_parity(uint32_t addr, uint32_t parity) {
    uint32_t done;
    asm volatile("{\n\t.reg .pred p;\n\t"
                 "mbarrier.try_wait.parity.acquire.cta.shared::cta.b64 p, [%1], %2;\n\t"
                 "selp.b32 %0, 1, 0, p;\n\t}"
                 : "=r"(done) : "r"(addr), "r"(parity) : "memory");
    while (!done) {
        asm volatile("{\n\t.reg .pred p;\n\t"
                     "mbarrier.try_wait.parity.acquire.cta.shared::cta.b64 p, [%1], %2, 0x989680;\n\t"
                     "selp.b32 %0, 1, 0, p;\n\t}"
                     : "=r"(done) : "r"(addr), "r"(parity) : "memory");
    }
}
__device__ __forceinline__ void cluster_sync_asm() {
    asm volatile("barrier.cluster.arrive.aligned;" ::: "memory");
    asm volatile("barrier.cluster.wait.aligned;" ::: "memory");
}

// ---------------------------------------------------------------------------
// Kernel 1: pack coords [N,3] AoS -> float4
// ---------------------------------------------------------------------------
__global__ void pack_kernel(const float* __restrict__ coord) {
    int i = blockIdx.x * blockDim.x + threadIdx.x;
    if (i < Bn * Nn) {
        g_packed[i] = make_float4(coord[3 * i], coord[3 * i + 1],
                                  coord[3 * i + 2], 0.f);
    }
}

// ---------------------------------------------------------------------------
// FPS body: cluster of C CTAs per batch, T threads/CTA, 4 points/thread.
// Candidates travel as packed u64 keys: (f32 bits of d2) << 32 | (0xFFFFFFFF -
// local_idx). max(key) == argmax by (d2, then smaller idx) (jnp.argmax ties).
// Per iteration: warp key-reduce -> CTA key-reduce (warp0) -> st.async push of
// (key, x, y, z) into every CTA's candidate slots + remote mbarrier
// complete_tx -> try_wait -> lane-parallel pick -> register dist update fused
// with next candidate. No cluster.sync in the loop.
// ---------------------------------------------------------------------------
template<int C, int T>
__device__ __forceinline__ void fps_body() {
    constexpr int P   = 4;
    constexpr int NW  = T / 32;          // warps per CTA
    constexpr int PTS = T * P;           // points per CTA
    constexpr int LGR = (PTS == 2048) ? 11 : 12;   // local_idx >> LGR == rank
    constexpr uint32_t TXB = 20u * C;    // bytes per exchange phase

    __shared__ unsigned long long slotK[NW];
    __shared__ float slotX[NW], slotY[NW], slotZ[NW];
    __shared__ unsigned long long candK[2][C];
    __shared__ unsigned long long candXY[2][C];
    __shared__ float              candZ[2][C];
    __shared__ unsigned long long mbarrier_s[2];

    const unsigned FULL = 0xffffffffu;
    int tid = threadIdx.x, lane = tid & 31, wid = tid >> 5;
    uint32_t rank = ctarank();
    int b = blockIdx.x / C;
    uint32_t local_base = rank * PTS + tid * P;    // idx within the batch
    uint32_t inv_base = 0xFFFFFFFFu - local_base;
    int gbase = b * Nn + (int)local_base;

    uint32_t mb0 = s2u(&mbarrier_s[0]), mb1 = s2u(&mbarrier_s[1]);
    if (tid == 0) { mbar_init(mb0, 1); mbar_init(mb1, 1); }

    float px[P], py[P], pz[P], dist[P];
#pragma unroll
    for (int j = 0; j < P; j++) {
        float4 q = g_packed[gbase + j];
        px[j] = q.x; py[j] = q.y; pz[j] = q.z;
    }

    // init: distance to point 0 of this batch (state after selecting s0 = 0)
    float4 p0 = g_packed[b * Nn];
    unsigned long long bkey = 0ull;
    float bx = 0.f, by = 0.f, bz = 0.f;
#pragma unroll
    for (int j = 0; j < P; j++) {
        float d = d2f(px[j], py[j], pz[j], p0.x, p0.y, p0.z);
        dist[j] = d;
        unsigned long long key = ((unsigned long long)__float_as_uint(d) << 32)
                               | (unsigned long long)(uint32_t)(inv_base - j);
        if (key > bkey) { bkey = key; bx = px[j]; by = py[j]; bz = pz[j]; }
    }
    if (rank == 0 && tid == 0) g_sidx[b * NGn + 0] = b * Nn;

    __syncthreads();
    cluster_sync_asm();   // all mbarriers initialized before any st.async

    for (int k = 1; k < NGn; k++) {
        int kb = k & 1;
        uint32_t parity = (uint32_t)(((k - 1) >> 1) & 1);
        uint32_t mbk = kb ? mb1 : mb0;
        if (tid == 0) mbar_expect_tx(mbk, TXB);

        // warp key-reduce; recover winner lane from idx bits, pull coords
        unsigned long long wk = bkey;
#pragma unroll
        for (int o = 16; o; o >>= 1) {
            unsigned long long ok = __shfl_xor_sync(FULL, wk, o);
            if (ok > wk) wk = ok;
        }
        uint32_t wloc = 0xFFFFFFFFu - (uint32_t)wk;
        int srcLane = (int)((wloc >> 2) & 31u);
        float sx = __shfl_sync(FULL, bx, srcLane);
        float sy = __shfl_sync(FULL, by, srcLane);
        float sz = __shfl_sync(FULL, bz, srcLane);
        if (lane == 0) {
            slotK[wid] = wk; slotX[wid] = sx; slotY[wid] = sy; slotZ[wid] = sz;
        }
        __syncthreads();

        if (wid == 0) {
            unsigned long long k0 = (lane < NW) ? slotK[lane] : 0ull;
#pragma unroll
            for (int o = NW / 2; o; o >>= 1) {
                unsigned long long ok = __shfl_xor_sync(FULL, k0, o);
                if (ok > k0) k0 = ok;
            }
            uint32_t cl = 0xFFFFFFFFu - (uint32_t)k0;
            int wwid = (int)((cl & (uint32_t)(PTS - 1)) >> 7);
            float cx = slotX[wwid], cy = slotY[wwid], cz = slotZ[wwid];
            if (lane < C) {
                uint32_t rk  = mapa_u32(s2u(&candK[kb][rank]),  (uint32_t)lane);
                uint32_t rxy = mapa_u32(s2u(&candXY[kb][rank]), (uint32_t)lane);
                uint32_t rz  = mapa_u32(s2u(&candZ[kb][rank]),  (uint32_t)lane);
                uint32_t rmb = mapa_u32(mbk, (uint32_t)lane);
                st_async_u64(rk, k0, rmb);
                unsigned long long xy =
                    ((unsigned long long)__float_as_uint(cy) << 32) | __float_as_uint(cx);
                st_async_u64(rxy, xy, rmb);
                st_async_u32(rz, __float_as_uint(cz), rmb);
            }
        }

        mbar_wait_parity(mbk, parity);

        // lane-parallel pick of the global winner among C candidates
        unsigned long long ck = (lane < C) ? candK[kb][lane] : 0ull;
#pragma unroll
        for (int o = C / 2; o; o >>= 1) {
            unsigned long long ok = __shfl_xor_sync(FULL, ck, o);
            if (ok > ck) ck = ok;
        }
        ck = __shfl_sync(FULL, ck, 0);
        uint32_t wl = 0xFFFFFFFFu - (uint32_t)ck;
        uint32_t wrank = wl >> LGR;
        unsigned long long xy = candXY[kb][wrank];
        float wx = __uint_as_float((uint32_t)xy);
        float wy = __uint_as_float((uint32_t)(xy >> 32));
        float wz = candZ[kb][wrank];
        if (rank == 0 && tid == 0) g_sidx[b * NGn + k] = b * Nn + (int)wl;

        // dist update fused with next candidate search
        bkey = 0ull;
#pragma unroll
        for (int j = 0; j < P; j++) {
            float nd = d2f(px[j], py[j], pz[j], wx, wy, wz);
            float mn = fminf(dist[j], nd);
            dist[j] = mn;
            unsigned long long key =
                ((unsigned long long)__float_as_uint(mn) << 32)
                | (unsigned long long)(uint32_t)(inv_base - j);
            if (key > bkey) { bkey = key; bx = px[j]; by = py[j]; bz = pz[j]; }
        }
    }
}

__global__ void __cluster_dims__(16, 1, 1) __launch_bounds__(512, 1)
fps_kernel16() { fps_body<16, 512>(); }

__global__ void __cluster_dims__(8, 1, 1) __launch_bounds__(1024, 1)
fps_kernel8() { fps_body<8, 1024>(); }

// ---------------------------------------------------------------------------
// Kernel 3: kNN (top-32 by (d2, idx) lex order) + angle/curvature + outputs.
// ---------------------------------------------------------------------------
__global__ void __launch_bounds__(1024, 1)
knn_kernel(const float* __restrict__ coord, const float* __restrict__ feat,
           const int* __restrict__ labels, float* __restrict__ out) {
    __shared__ float4 sc[CHUNK];
    const unsigned FULL = 0xffffffffu;
    int tid = threadIdx.x, lane = tid & 31, wid = tid >> 5;
    int s = blockIdx.x * 32 + wid;   // sample id [0, 8192)
    int b = s >> 10;                 // batch (1024 samples/batch)
    int si = g_sidx[s];              // global point idx of this sample
    float4 sp = g_packed[si];

    float kd = 3.4028235e38f; int ki = 0x7fffffff;          // kept (per lane)
    float tmd = 3.4028235e38f; int tmi = 0x7fffffff; int tml = 0;  // lex-max

    for (int c = 0; c < Nn / CHUNK; c++) {
        int cb = c * CHUNK;
        __syncthreads();
#pragma unroll
        for (int e = tid; e < CHUNK; e += 1024)
            sc[e] = g_packed[b * Nn + cb + e];
        __syncthreads();
        for (int j = 0; j < CHUNK / 32; j++) {
            float4 q = sc[j * 32 + lane];
            int gi = b * Nn + cb + j * 32 + lane;
            float d2 = d2f(sp.x, sp.y, sp.z, q.x, q.y, q.z);
            unsigned m = __ballot_sync(FULL, (d2 < tmd) || (d2 == tmd && gi < tmi));
            while (m) {
                int src = __ffs(m) - 1; m &= m - 1;
                float cd = __shfl_sync(FULL, d2, src);
                int   ci = __shfl_sync(FULL, gi, src);
                if ((cd < tmd) || (cd == tmd && ci < tmi)) {   // uniform branch
                    if (lane == tml) { kd = cd; ki = ci; }
                    float md = kd; int mi = ki; int ml = lane;
#pragma unroll
                    for (int o = 16; o; o >>= 1) {
                        float od = __shfl_xor_sync(FULL, md, o);
                        int   oi = __shfl_xor_sync(FULL, mi, o);
                        int   ol = __shfl_xor_sync(FULL, ml, o);
                        if (od > md || (od == md && (oi < mi || (oi == mi && ol < ml)))) {
                            md = od; mi = oi; ml = ol;
                        }
                    }
                    tmd = md; tmi = mi; tml = ml;
                }
            }
        }
    }

    // ---- angles: angle = 2*atan2(sqrt(t - a.b), sqrt(t + a.b)), t=|a||b| ----
    float a_own = feat[si * FDn + lane];
    float dot = 0.f, an2 = 0.f, bn2 = 0.f;
    const float4* frow = (const float4*)(feat + (size_t)ki * FDn);
#pragma unroll
    for (int g = 0; g < FDn / 4; g++) {
        float4 bv = frow[g];
        float a0 = __shfl_sync(FULL, a_own, g * 4 + 0);
        float a1 = __shfl_sync(FULL, a_own, g * 4 + 1);
        float a2 = __shfl_sync(FULL, a_own, g * 4 + 2);
        float a3 = __shfl_sync(FULL, a_own, g * 4 + 3);
        dot = fmaf(a0, bv.x, dot); an2 = fmaf(a0, a0, an2); bn2 = fmaf(bv.x, bv.x, bn2);
        dot = fmaf(a1, bv.y, dot); an2 = fmaf(a1, a1, an2); bn2 = fmaf(bv.y, bv.y, bn2);
        dot = fmaf(a2, bv.z, dot); an2 = fmaf(a2, a2, an2); bn2 = fmaf(bv.z, bv.z, bn2);
        dot = fmaf(a3, bv.w, dot); an2 = fmaf(a3, a3, an2); bn2 = fmaf(bv.w, bv.w, bn2);
    }
    float t = sqrtf(an2) * sqrtf(bn2);
    float ang = 2.f * atan2f(sqrtf(fmaxf(t - dot, 0.f)), sqrtf(fmaxf(t + dot, 0.f)));
    if (ki == si) ang = 0.f;   // exclude self (the sorted-nearest neighbor)
    float ssum = ang;
#pragma unroll
    for (int o = 16; o; o >>= 1) ssum += __shfl_xor_sync(FULL, ssum, o);
    float pc = ssum / 31.f;

    // ---- outputs (tuple flattened+concatenated as float32) ----
    const int OFF_FEAT = Bn * NGn * 3;
    const int OFF_SW   = OFF_FEAT + Bn * NGn * (FDn + 1);
    const int OFF_LAB  = OFF_SW + Bn * NGn;
    const int OFF_SIDX = OFF_LAB + Bn * NGn;
    if (lane < 3) out[s * 3 + lane] = coord[si * 3 + lane];
    out[OFF_FEAT + s * 33 + lane] = a_own;
    if (lane == 0) {
        out[OFF_FEAT + s * 33 + 32] = pc;
        out[OFF_SW + s]   = pc > 0.087266f ? 1.f : 0.f;
        out[OFF_LAB + s]  = (float)labels[si];
        out[OFF_SIDX + s] = (float)si;
    }
}

// ---------------------------------------------------------------------------
extern "C" void kernel_launch(void* const* d_in, const int* in_sizes, int n_in,
                              void* d_out, int out_size) {
    const float* coord  = (const float*)d_in[0];
    const float* feat   = (const float*)d_in[1];
    const int*   labels = (const int*)d_in[2];
    float* out = (float*)d_out;

    pack_kernel<<<(Bn * Nn + 255) / 256, 256>>>(coord);

    cudaError_t rc = cudaFuncSetAttribute(
        (const void*)fps_kernel16,
        cudaFuncAttributeNonPortableClusterSizeAllowed, 1);
    if (rc == cudaSuccess) {
        fps_kernel16<<<Bn * 16, 512>>>();
    } else {
        (void)cudaGetLastError();
        fps_kernel8<<<Bn * 8, 1024>>>();
    }

    knn_kernel<<<(Bn * NGn) / 32, 1024>>>(coord, feat, labels, out);
}

// round 3
// speedup vs baseline: 2.2010x; 1.6419x over previous
#include <cuda_runtime.h>
#include <cstdint>

#define Bn   8
#define Nn   32768
#define FDn  32
#define NGn  1024
#define CHUNK 2048    // kNN smem tile (points)

// Scratch (no allocations allowed): packed coords + FPS-selected indices
__device__ float4 g_packed[Bn * Nn];     // 4 MB
__device__ int    g_sidx[Bn * NGn];      // global point index of each sample

// Exact (non-FMA, left-to-right) squared distance, matching XLA's
// sum((a-b)**2) elementwise f32 semantics.
__device__ __forceinline__ float d2f(float ax, float ay, float az,
                                     float bx, float by, float bz) {
    float dx = ax - bx, dy = ay - by, dz = az - bz;
    return __fadd_rn(__fadd_rn(__fmul_rn(dx, dx), __fmul_rn(dy, dy)),
                     __fmul_rn(dz, dz));
}

// ---------------------------------------------------------------------------
// small PTX helpers
// ---------------------------------------------------------------------------
__device__ __forceinline__ uint32_t s2u(const void* p) {
    return (uint32_t)__cvta_generic_to_shared(p);
}
__device__ __forceinline__ uint32_t ctarank() {
    uint32_t r; asm("mov.u32 %0, %%cluster_ctarank;" : "=r"(r)); return r;
}
__device__ __forceinline__ uint32_t mapa_u32(uint32_t addr, uint32_t rank) {
    uint32_t r;
    asm("mapa.shared::cluster.u32 %0, %1, %2;" : "=r"(r) : "r"(addr), "r"(rank));
    return r;
}
__device__ __forceinline__ void st_async_u64(uint32_t raddr, unsigned long long v,
                                             uint32_t rmbar) {
    asm volatile("st.async.shared::cluster.mbarrier::complete_tx::bytes.u64 [%0], %1, [%2];"
                 :: "r"(raddr), "l"(v), "r"(rmbar) : "memory");
}
__device__ __forceinline__ void st_async_u32(uint32_t raddr, uint32_t v,
                                             uint32_t rmbar) {
    asm volatile("st.async.shared::cluster.mbarrier::complete_tx::bytes.u32 [%0], %1, [%2];"
                 :: "r"(raddr), "r"(v), "r"(rmbar) : "memory");
}
__device__ __forceinline__ void mbar_init(uint32_t addr, uint32_t cnt) {
    asm volatile("mbarrier.init.shared.b64 [%0], %1;" :: "r"(addr), "r"(cnt) : "memory");
}
__device__ __forceinline__ void mbar_expect_tx(uint32_t addr, uint32_t bytes) {
    asm volatile("mbarrier.arrive.expect_tx.shared.b64 _, [%0], %1;"
                 :: "r"(addr), "r"(bytes) : "memory");
}
__device__ __forceinline__ void mbar_wait_parity(uint32_t addr, uint32_t parity) {
    uint32_t done;
    asm volatile("{\n\t.reg .pred p;\n\t"
                 "mbarrier.try_wait.parity.acquire.cta.shared::cta.b64 p, [%1], %2;\n\t"
                 "selp.b32 %0, 1, 0, p;\n\t}"
                 : "=r"(done) : "r"(addr), "r"(parity) : "memory");
    while (!done) {
        asm volatile("{\n\t.reg .pred p;\n\t"
                     "mbarrier.try_wait.parity.acquire.cta.shared::cta.b64 p, [%1], %2, 0x989680;\n\t"
                     "selp.b32 %0, 1, 0, p;\n\t}"
                     : "=r"(done) : "r"(addr), "r"(parity) : "memory");
    }
}
__device__ __forceinline__ void cluster_sync_asm() {
    asm volatile("barrier.cluster.arrive.aligned;" ::: "memory");
    asm volatile("barrier.cluster.wait.aligned;" ::: "memory");
}

// ---------------------------------------------------------------------------
// Kernel 1: pack coords [N,3] AoS -> float4 (4 points per thread, f4 loads)
// ---------------------------------------------------------------------------
__global__ void pack_kernel(const float* __restrict__ coord) {
    int t = blockIdx.x * blockDim.x + threadIdx.x;   // handles points 4t..4t+3
    if (t * 4 >= Bn * Nn) return;
    const float4* c4 = (const float4*)(coord + (size_t)t * 12);
    float4 a = c4[0], b = c4[1], c = c4[2];
    g_packed[t * 4 + 0] = make_float4(a.x, a.y, a.z, 0.f);
    g_packed[t * 4 + 1] = make_float4(a.w, b.x, b.y, 0.f);
    g_packed[t * 4 + 2] = make_float4(b.z, b.w, c.x, 0.f);
    g_packed[t * 4 + 3] = make_float4(c.y, c.z, c.w, 0.f);
}

// ---------------------------------------------------------------------------
// FPS: cluster of C CTAs per batch, T threads/CTA, P points/thread.
// All argmax stages use redux.max on f32 bits (d2 >= 0 so bits are order-
// isomorphic) + ballot + ffs. Lane order == index order at every level, so
// ffs == smallest-index tie-break (jnp.argmax semantics). Candidate
// (d,idx,x,y,z) is exchanged all-to-all via st.async + mbarrier complete_tx.
// ---------------------------------------------------------------------------
template<int C, int T, int P>
__device__ __forceinline__ void fps_body() {
    constexpr int NW  = T / 32;          // warps per CTA
    constexpr int PTS = T * P;           // points per CTA
    constexpr uint32_t TXB = 20u * C;    // bytes per exchange phase

    __shared__ uint32_t slotD[NW], slotI[NW];
    __shared__ float    slotX[NW], slotY[NW], slotZ[NW];
    __shared__ unsigned long long candDI[2][C];
    __shared__ unsigned long long candXY[2][C];
    __shared__ uint32_t           candZ[2][C];
    __shared__ unsigned long long mbarrier_s[2];

    const unsigned FULL = 0xffffffffu;
    int tid = threadIdx.x, lane = tid & 31, wid = tid >> 5;
    uint32_t rank = ctarank();
    int b = blockIdx.x / C;
    uint32_t local_base = rank * PTS + (uint32_t)tid * P;   // idx within batch
    int gbase = b * Nn + (int)local_base;

    uint32_t mb0 = s2u(&mbarrier_s[0]), mb1 = s2u(&mbarrier_s[1]);
    if (tid == 0) { mbar_init(mb0, 1); mbar_init(mb1, 1); }

    // hoisted remote addresses (used only by warp0 lanes < C)
    uint32_t rDI[2], rXY[2], rZ[2], rMB[2];
    if (wid == 0 && lane < C) {
#pragma unroll
        for (int q = 0; q < 2; q++) {
            rDI[q] = mapa_u32(s2u(&candDI[q][rank]), (uint32_t)lane);
            rXY[q] = mapa_u32(s2u(&candXY[q][rank]), (uint32_t)lane);
            rZ[q]  = mapa_u32(s2u(&candZ[q][rank]),  (uint32_t)lane);
            rMB[q] = mapa_u32(q ? mb1 : mb0, (uint32_t)lane);
        }
    }

    float px[P], py[P], pz[P], dist[P];
#pragma unroll
    for (int j = 0; j < P; j++) {
        float4 q = g_packed[gbase + j];
        px[j] = q.x; py[j] = q.y; pz[j] = q.z;
    }

    // init: distance to point 0 (state after selecting s0 = 0)
    float4 p0 = g_packed[b * Nn];
    float bd = -1.f; int bj = 0;
#pragma unroll
    for (int j = 0; j < P; j++) {
        float d = d2f(px[j], py[j], pz[j], p0.x, p0.y, p0.z);
        dist[j] = d;
        if (d > bd) { bd = d; bj = j; }   // strict > keeps smallest j (idx)
    }
    if (rank == 0 && tid == 0) g_sidx[b * NGn + 0] = b * Nn;

    __syncthreads();
    cluster_sync_asm();   // all mbarriers initialized before any st.async

    for (int k = 1; k < NGn; k++) {
        int kb = k & 1;
        uint32_t parity = (uint32_t)(((k - 1) >> 1) & 1);
        uint32_t mbk = kb ? mb1 : mb0;
        if (tid == 0) mbar_expect_tx(mbk, TXB);

        // select this lane's best point coords (bj is 0..P-1): sel tree
        float cx, cy, cz;
        {
            int j = bj;
#if (8 == 8)
#endif
            float x01 = (j & 1) ? px[1] : px[0];
            float y01 = (j & 1) ? py[1] : py[0];
            float z01 = (j & 1) ? pz[1] : pz[0];
            float x23 = (j & 1) ? px[3] : px[2];
            float y23 = (j & 1) ? py[3] : py[2];
            float z23 = (j & 1) ? pz[3] : pz[2];
            if (P == 8) {
                float x45 = (j & 1) ? px[5] : px[4];
                float y45 = (j & 1) ? py[5] : py[4];
                float z45 = (j & 1) ? pz[5] : pz[4];
                float x67 = (j & 1) ? px[7] : px[6];
                float y67 = (j & 1) ? py[7] : py[6];
                float z67 = (j & 1) ? pz[7] : pz[6];
                float xa = (j & 2) ? x23 : x01, xb = (j & 2) ? x67 : x45;
                float ya = (j & 2) ? y23 : y01, yb = (j & 2) ? y67 : y45;
                float za = (j & 2) ? z23 : z01, zb = (j & 2) ? z67 : z45;
                cx = (j & 4) ? xb : xa; cy = (j & 4) ? yb : ya; cz = (j & 4) ? zb : za;
            } else {
                cx = (j & 2) ? x23 : x01; cy = (j & 2) ? y23 : y01; cz = (j & 2) ? z23 : z01;
            }
        }
        uint32_t myidx = local_base + (uint32_t)bj;

        // warp argmax via redux + ballot (+ lane order == idx order)
        uint32_t dbits = __float_as_uint(bd);
        uint32_t wmax  = __reduce_max_sync(FULL, dbits);
        int wsrc = __ffs(__ballot_sync(FULL, dbits == wmax)) - 1;
        uint32_t widx = __shfl_sync(FULL, myidx, wsrc);
        float wx = __shfl_sync(FULL, cx, wsrc);
        float wy = __shfl_sync(FULL, cy, wsrc);
        float wz = __shfl_sync(FULL, cz, wsrc);
        if (lane == 0) {
            slotD[wid] = wmax; slotI[wid] = widx;
            slotX[wid] = wx; slotY[wid] = wy; slotZ[wid] = wz;
        }
        __syncthreads();

        if (wid == 0) {
            int sl = lane & (NW - 1);
            uint32_t d = (lane < NW) ? slotD[sl] : 0u;
            uint32_t i = slotI[sl];
            float x = slotX[sl], y = slotY[sl], z = slotZ[sl];
            uint32_t m = __reduce_max_sync(FULL, d);
            int src = __ffs(__ballot_sync(FULL, d == m)) - 1;
            uint32_t ci = __shfl_sync(FULL, i, src);
            float fx = __shfl_sync(FULL, x, src);
            float fy = __shfl_sync(FULL, y, src);
            float fz = __shfl_sync(FULL, z, src);
            if (lane < C) {
                st_async_u64(rDI[kb], ((unsigned long long)m << 32) | ci, rMB[kb]);
                unsigned long long xy =
                    ((unsigned long long)__float_as_uint(fy) << 32) | __float_as_uint(fx);
                st_async_u64(rXY[kb], xy, rMB[kb]);
                st_async_u32(rZ[kb], __float_as_uint(fz), rMB[kb]);
            }
        }

        mbar_wait_parity(mbk, parity);

        // cluster pick: lane r holds candidate of CTA r (rank order == idx order)
        int cl = lane & (C - 1);
        unsigned long long di = candDI[kb][cl];
        unsigned long long xy = candXY[kb][cl];
        uint32_t zz = candZ[kb][cl];
        uint32_t d = (lane < C) ? (uint32_t)(di >> 32) : 0u;
        uint32_t m = __reduce_max_sync(FULL, d);
        int src = __ffs(__ballot_sync(FULL, d == m)) - 1;
        uint32_t wl = __shfl_sync(FULL, (uint32_t)di, src);
        unsigned long long wxy = __shfl_sync(FULL, xy, src);
        uint32_t wzb = __shfl_sync(FULL, zz, src);
        float gx = __uint_as_float((uint32_t)wxy);
        float gy = __uint_as_float((uint32_t)(wxy >> 32));
        float gz = __uint_as_float(wzb);
        if (rank == 0 && tid == 0) g_sidx[b * NGn + k] = b * Nn + (int)wl;

        // dist update fused with next candidate search
        bd = -1.f; bj = 0;
#pragma unroll
        for (int j = 0; j < P; j++) {
            float nd = d2f(px[j], py[j], pz[j], gx, gy, gz);
            float mn = fminf(dist[j], nd);
            dist[j] = mn;
            if (mn > bd) { bd = mn; bj = j; }
        }
    }
}

__global__ void __cluster_dims__(16, 1, 1) __launch_bounds__(256, 1)
fps_kernel16() { fps_body<16, 256, 8>(); }

__global__ void __cluster_dims__(8, 1, 1) __launch_bounds__(1024, 1)
fps_kernel8() { fps_body<8, 1024, 4>(); }

// ---------------------------------------------------------------------------
// Kernel 3: kNN (top-32 by (d2, idx) lex order) + angle/curvature + outputs.
// 512 threads = 16 warps; one warp per sample; 32KB coord tile shared by CTA.
// ---------------------------------------------------------------------------
__global__ void __launch_bounds__(512, 1)
knn_kernel(const float* __restrict__ coord, const float* __restrict__ feat,
           const int* __restrict__ labels, float* __restrict__ out) {
    __shared__ float4 sc[CHUNK];
    const unsigned FULL = 0xffffffffu;
    int tid = threadIdx.x, lane = tid & 31, wid = tid >> 5;
    int s = blockIdx.x * 16 + wid;   // sample id [0, 8192)
    int b = s >> 10;                 // batch (1024 samples/batch)
    int si = g_sidx[s];              // global point idx of this sample
    float4 sp = g_packed[si];

    float kd = 3.4028235e38f; unsigned ki = 0xffffffffu;    // kept (per lane)
    float tmd = 3.4028235e38f; unsigned tmi = 0xffffffffu; int tml = 0;

    for (int c = 0; c < Nn / CHUNK; c++) {
        int cb = c * CHUNK;
        __syncthreads();
#pragma unroll
        for (int e = tid; e < CHUNK; e += 512)
            sc[e] = g_packed[b * Nn + cb + e];
        __syncthreads();
        for (int j = 0; j < CHUNK / 32; j++) {
            float4 q = sc[j * 32 + lane];
            unsigned gi = (unsigned)(b * Nn + cb + j * 32 + lane);
            float d2 = d2f(sp.x, sp.y, sp.z, q.x, q.y, q.z);
            unsigned mask = __ballot_sync(FULL, (d2 < tmd) || (d2 == tmd && gi < tmi));
            while (mask) {
                int ins = __ffs(mask) - 1; mask &= mask - 1;
                float cd = __shfl_sync(FULL, d2, ins);
                unsigned cgi = __shfl_sync(FULL, gi, ins);
                if ((cd < tmd) || (cd == tmd && cgi < tmi)) {   // uniform branch
                    if (lane == tml) { kd = cd; ki = cgi; }
                    // recompute kept-set lex-max (d2, then LARGER idx is worse)
                    unsigned db = __float_as_uint(kd);
                    unsigned m  = __reduce_max_sync(FULL, db);
                    bool tie    = (db == m);
                    unsigned cand = tie ? ki : 0u;
                    unsigned mi2  = __reduce_max_sync(FULL, cand);
                    tml = __ffs(__ballot_sync(FULL, tie && ki == mi2)) - 1;
                    tmd = __uint_as_float(m);
                    tmi = mi2;
                }
            }
        }
    }

    // ---- angles: angle = 2*atan2(sqrt(t - a.b), sqrt(t + a.b)), t=|a||b| ----
    float a_own = feat[(size_t)si * FDn + lane];
    float dot = 0.f, an2 = 0.f, bn2 = 0.f;
    const float4* frow = (const float4*)(feat + (size_t)ki * FDn);
#pragma unroll
    for (int g = 0; g < FDn / 4; g++) {
        float4 bv = frow[g];
        float a0 = __shfl_sync(FULL, a_own, g * 4 + 0);
        float a1 = __shfl_sync(FULL, a_own, g * 4 + 1);
        float a2 = __shfl_sync(FULL, a_own, g * 4 + 2);
        float a3 = __shfl_sync(FULL, a_own, g * 4 + 3);
        dot = fmaf(a0, bv.x, dot); an2 = fmaf(a0, a0, an2); bn2 = fmaf(bv.x, bv.x, bn2);
        dot = fmaf(a1, bv.y, dot); an2 = fmaf(a1, a1, an2); bn2 = fmaf(bv.y, bv.y, bn2);
        dot = fmaf(a2, bv.z, dot); an2 = fmaf(a2, a2, an2); bn2 = fmaf(bv.z, bv.z, bn2);
        dot = fmaf(a3, bv.w, dot); an2 = fmaf(a3, a3, an2); bn2 = fmaf(bv.w, bv.w, bn2);
    }
    float t = sqrtf(an2) * sqrtf(bn2);
    float ang = 2.f * atan2f(sqrtf(fmaxf(t - dot, 0.f)), sqrtf(fmaxf(t + dot, 0.f)));
    if (ki == (unsigned)si) ang = 0.f;   // self neighbor contributes 0
    float ssum = ang;
#pragma unroll
    for (int o = 16; o; o >>= 1) ssum += __shfl_xor_sync(FULL, ssum, o);
    float pc = ssum / 31.f;

    // ---- outputs (tuple flattened+concatenated as float32) ----
    const int OFF_FEAT = Bn * NGn * 3;
    const int OFF_SW   = OFF_FEAT + Bn * NGn * (FDn + 1);
    const int OFF_LAB  = OFF_SW + Bn * NGn;
    const int OFF_SIDX = OFF_LAB + Bn * NGn;
    if (lane < 3) out[s * 3 + lane] = coord[si * 3 + lane];
    out[OFF_FEAT + s * 33 + lane] = a_own;
    if (lane == 0) {
        out[OFF_FEAT + s * 33 + 32] = pc;
        out[OFF_SW + s]   = pc > 0.087266f ? 1.f : 0.f;
        out[OFF_LAB + s]  = (float)labels[si];
        out[OFF_SIDX + s] = (float)si;
    }
}

// ---------------------------------------------------------------------------
extern "C" void kernel_launch(void* const* d_in, const int* in_sizes, int n_in,
                              void* d_out, int out_size) {
    const float* coord  = (const float*)d_in[0];
    const float* feat   = (const float*)d_in[1];
    const int*   labels = (const int*)d_in[2];
    float* out = (float*)d_out;

    pack_kernel<<<(Bn * Nn / 4 + 255) / 256, 256>>>(coord);

    cudaError_t rc = cudaFuncSetAttribute(
        (const void*)fps_kernel16,
        cudaFuncAttributeNonPortableClusterSizeAllowed, 1);
    if (rc == cudaSuccess) {
        fps_kernel16<<<Bn * 16, 256>>>();
    } else {
        (void)cudaGetLastError();
        fps_kernel8<<<Bn * 8, 1024>>>();
    }

    knn_kernel<<<(Bn * NGn) / 16, 512>>>(coord, feat, labels, out);
}